// round 17
// baseline (speedup 1.0000x reference)
#include <cuda_runtime.h>
#include <cuda_bf16.h>
#include <math.h>
#include <stdint.h>

#define BQ   16
#define TT   1000
#define MEL  80
#define HID  512
#define NCLS 64
#define NROW (BQ*TT)

#define CLN  8       // CTAs per cluster  (8 clusters x 8 CTAs = 64 -- proven placement)
#define NCTA 64
#define BPC  2       // batch elements per cluster

#define WROWB 1040u                 // bf16 row stride bytes (1024 + 16 pad)
#define WMATB (64u*WROWB)           // 66560 B per matrix slice
#define DYNSM (2u*WMATB)            // 133120 B

#define HROWS 16                    // k_head rows per block (64KB dyn -> 2 CTA/SM)
#define HEAD_DYN (HROWS*1024*4)     // 65536 B

// ---------------- scratch (static device globals; no allocations) ----------------
__device__ float g_be0[NROW*HID];
__device__ float g_be1[NROW*HID];
__device__ float g_h1 [NROW*HID];
__device__ float g_xs1[NROW];

__device__ __forceinline__ float sigm(float x){ return 1.0f/(1.0f+expf(-x)); }

__device__ __forceinline__ uint32_t smem_u32(const void* p){
  uint32_t a;
  asm("{ .reg .u64 t; cvta.to.shared.u64 t, %1; cvt.u32.u64 %0, t; }" : "=r"(a) : "l"(p));
  return a;
}
__device__ __forceinline__ void dsmem_st4(uint32_t laddr, uint32_t rnk, float4 v){
  uint32_t ra;
  asm volatile("mapa.shared::cluster.u32 %0, %1, %2;" : "=r"(ra) : "r"(laddr), "r"(rnk));
  asm volatile("st.shared::cluster.v4.f32 [%0], {%1,%2,%3,%4};"
               :: "r"(ra), "f"(v.x), "f"(v.y), "f"(v.z), "f"(v.w) : "memory");
}
__device__ __forceinline__ void dsmem_st1(uint32_t laddr, uint32_t rnk, float v){
  uint32_t ra;
  asm volatile("mapa.shared::cluster.u32 %0, %1, %2;" : "=r"(ra) : "r"(laddr), "r"(rnk));
  asm volatile("st.shared::cluster.f32 [%0], %1;" :: "r"(ra), "f"(v) : "memory");
}
#define CLUSTER_ARRIVE() asm volatile("barrier.cluster.arrive.aligned;" ::: "memory")
#define CLUSTER_WAIT()   asm volatile("barrier.cluster.wait.aligned;"   ::: "memory")

// packed f32x2 FMA helpers
__device__ __forceinline__ void ffma2(unsigned long long& a, unsigned long long w,
                                      unsigned long long x){
  asm("fma.rn.f32x2 %0, %1, %2, %0;" : "+l"(a) : "l"(w), "l"(x));
}
__device__ __forceinline__ float hsum2(unsigned long long a){
  return __uint_as_float((unsigned)(a & 0xffffffffu)) +
         __uint_as_float((unsigned)(a >> 32));
}
// unpack a bf16x2 word into an f32x2 pair (transient; ptxas can pair-allocate)
__device__ __forceinline__ unsigned long long bf2pair(uint32_t w){
  unsigned long long p;
  asm("{ .reg .b32 lo,hi;\n\t"
      "shl.b32 lo, %1, 16;\n\t"
      "and.b32 hi, %1, 0xffff0000;\n\t"
      "mov.b64 %0, {lo,hi}; }"
      : "=l"(p) : "r"(w));
  return p;
}

// permuted float4-group position for x buffers: group g (=k/4) -> pos
__host__ __device__ __forceinline__ int xpos(int g){
  int j = g>>1;
  return ((j>>4)<<5) + ((g&1)<<4) + (j&15);
}

// ---------------- fused front: be0 + xs1 + be1 (row-local chain) ------------------
// Phase A == old k_be0 (bit-identical math); be0 tile additionally kept in smem.
// Phase B == old k_be1 reading the smem tile (same values -> bit-identical be1).
__global__ __launch_bounds__(256) void k_front(const float* __restrict__ feats,
                                               const float* __restrict__ B0,
                                               const float* __restrict__ B1){
  __shared__ float xf[16][MEL];
  __shared__ float snorm[16];
  __shared__ float sxs[16];
  __shared__ float sxs1[16];
  __shared__ __align__(16) float be0s[16][HID];   // 32KB
  int tid = threadIdx.x;
  int row0 = blockIdx.x*16;

  // ---- phase A: be0 ----
  for (int i=tid;i<16*MEL;i+=256)
    xf[i/MEL][i%MEL] = feats[row0*MEL + i];
  __syncthreads();
  if (tid<16){
    float s=0.f;
    #pragma unroll
    for (int k=0;k<MEL;k++){ float v=xf[tid][k]; s+=v*v; }
    sxs[tid]=fmaxf(sqrtf(s),1e-6f);
    snorm[tid]=0.f;
  }
  __syncthreads();
  for (int i=tid;i<16*MEL;i+=256){
    int r=i/MEL;
    float v = xf[r][i%MEL]/sxs[r];
    xf[r][i%MEL] = fminf(fmaxf(v,-1.f),1.f);
  }
  __syncthreads();
  int n0=tid, n1=tid+256;
  {
    float a0[16], a1_[16];
    #pragma unroll
    for (int r=0;r<16;r++){ a0[r]=0.f; a1_[r]=0.f; }
    for (int k=0;k<MEL;k+=4){
      float4 w0 = *(const float4*)&B0[n0*MEL+k];
      float4 w1 = *(const float4*)&B0[n1*MEL+k];
      #pragma unroll
      for (int r=0;r<16;r++){
        float4 x = *(const float4*)&xf[r][k];
        a0 [r] += w0.x*x.x + w0.y*x.y + w0.z*x.z + w0.w*x.w;
        a1_[r] += w1.x*x.x + w1.y*x.y + w1.z*x.z + w1.w*x.w;
      }
    }
    #pragma unroll
    for (int r=0;r<16;r++){
      g_be0[(row0+r)*HID+n0]=a0[r];
      g_be0[(row0+r)*HID+n1]=a1_[r];
      be0s[r][n0]=a0[r];
      be0s[r][n1]=a1_[r];
      atomicAdd(&snorm[r], a0[r]*a0[r] + a1_[r]*a1_[r]);
    }
  }
  __syncthreads();
  if (tid<16){
    float v = fmaxf(sqrtf(snorm[tid]),1e-6f);
    g_xs1[row0+tid] = v;
    sxs1[tid] = v;
  }
  __syncthreads();

  // ---- phase B: be1 (normalize smem tile in place, then GEMM vs B1) ----
  for (int i=tid;i<16*HID;i+=256){
    int r=i>>9;
    float v = (&be0s[0][0])[i]/sxs1[r];
    (&be0s[0][0])[i] = fminf(fmaxf(v,-1.f),1.f);
  }
  __syncthreads();
  {
    float a0[16], a1_[16];
    #pragma unroll
    for (int r=0;r<16;r++){ a0[r]=0.f; a1_[r]=0.f; }
    for (int k=0;k<HID;k+=4){
      float4 w0 = *(const float4*)&B1[n0*HID+k];
      float4 w1 = *(const float4*)&B1[n1*HID+k];
      #pragma unroll
      for (int r=0;r<16;r++){
        float4 x = *(const float4*)&be0s[r][k];
        a0 [r] += w0.x*x.x + w0.y*x.y + w0.z*x.z + w0.w*x.w;
        a1_[r] += w1.x*x.x + w1.y*x.y + w1.z*x.z + w1.w*x.w;
      }
    }
    #pragma unroll
    for (int r=0;r<16;r++){
      g_be1[(row0+r)*HID+n0]=a0[r];
      g_be1[(row0+r)*HID+n1]=a1_[r];
    }
  }
}

// ---------------- serial recurrence (R15 EXACT -- proven 3860us) ------------------
__device__ __forceinline__ void dot_bf16(const uint8_t* __restrict__ wsm,
                                         const uint8_t* __restrict__ xb,
                                         int rg, int kq, float* __restrict__ acc){
  const uint8_t* wr = wsm + (unsigned)(rg*4)*WROWB + (unsigned)kq*16u;
  unsigned long long aA[4]={0ull,0ull,0ull,0ull}, aB[4]={0ull,0ull,0ull,0ull};
  #pragma unroll
  for (int m=0;m<4;m++){
    ulonglong2 xa0 = *(const ulonglong2*)(xb + (m*32+kq)*16);
    ulonglong2 xa1 = *(const ulonglong2*)(xb + (m*32+16+kq)*16);
    ulonglong2 xb0 = *(const ulonglong2*)(xb + 2048 + (m*32+kq)*16);
    ulonglong2 xb1 = *(const ulonglong2*)(xb + 2048 + (m*32+16+kq)*16);
    #pragma unroll
    for (int r=0;r<4;r++){
      uint4 w = *(const uint4*)(wr + (unsigned)r*WROWB + (unsigned)m*256u);
      unsigned long long p0 = bf2pair(w.x);
      unsigned long long p1 = bf2pair(w.y);
      unsigned long long p2 = bf2pair(w.z);
      unsigned long long p3 = bf2pair(w.w);
      ffma2(aA[r], p0, xa0.x); ffma2(aA[r], p1, xa0.y);
      ffma2(aA[r], p2, xa1.x); ffma2(aA[r], p3, xa1.y);
      ffma2(aB[r], p0, xb0.x); ffma2(aB[r], p1, xb0.y);
      ffma2(aB[r], p2, xb1.x); ffma2(aB[r], p3, xb1.y);
    }
  }
  #pragma unroll
  for (int r=0;r<4;r++){ acc[r*2]=hsum2(aA[r]); acc[r*2+1]=hsum2(aB[r]); }
}

__global__ __launch_bounds__(256,1) __cluster_dims__(CLN,1,1)
void k_serial(const float* __restrict__ C1, const float* __restrict__ W1,
              const float* __restrict__ a1, const float* __restrict__ tau,
              const float* __restrict__ gam){
  extern __shared__ __align__(16) uint8_t dynsm[];
  uint8_t* wsmC = dynsm;                 // [64][WROWB] bf16
  uint8_t* wsmW = dynsm + WMATB;

  __shared__ __align__(16) float hbufP[BPC][HID];    // permuted h   (remote-written)
  __shared__ __align__(16) float ebufP[BPC][HID];    // permuted err (remote-written)
  __shared__ __align__(16) float estageP[BPC][64];
  __shared__ __align__(16) float hstageP[BPC][64];
  __shared__ float2 pout2[64];
  __shared__ float narr[BPC][CLN];
  __shared__ float normloc[2][BPC];                  // ping-pong by step parity
  __shared__ float sa[64];

  const int tid  = threadIdx.x;
  const int rank = blockIdx.x & (CLN-1);
  const int b0   = (blockIdx.x / CLN) * BPC;
  const int rg   = tid >> 4, kq = tid & 15;
  const float tauv = __ldg(&tau[0]), gamv = __ldg(&gam[0]);

  for (int i=tid; i<64*128; i+=256){
    int r=i>>7, q=i&127;
    float4 vc = __ldg((const float4*)&C1[(rank*64+r)*HID + q*4]);
    float4 vw = __ldg((const float4*)&W1[(rank*64+r)*HID + q*4]);
    __nv_bfloat162 c0 = __floats2bfloat162_rn(vc.x, vc.y);
    __nv_bfloat162 c1 = __floats2bfloat162_rn(vc.z, vc.w);
    __nv_bfloat162 w0 = __floats2bfloat162_rn(vw.x, vw.y);
    __nv_bfloat162 w1 = __floats2bfloat162_rn(vw.z, vw.w);
    uint2 uc; uc.x = *(uint32_t*)&c0; uc.y = *(uint32_t*)&c1;
    uint2 uw; uw.x = *(uint32_t*)&w0; uw.y = *(uint32_t*)&w1;
    *(uint2*)(wsmC + (unsigned)r*WROWB + (unsigned)q*8u) = uc;
    *(uint2*)(wsmW + (unsigned)r*WROWB + (unsigned)q*8u) = uw;
  }
  for (int i=tid;i<BPC*HID;i+=256) (&hbufP[0][0])[i]=0.f;
  if (tid<2*BPC) (&normloc[0][0])[tid]=0.f;
  if (tid<64)  sa[tid] = sigm(__ldg(&a1[rank*64+tid]));
  __syncthreads();

  const uint32_t a_ebuf = smem_u32(&ebufP[0][0]);
  const uint32_t a_hbuf = smem_u32(&hbufP[0][0]);
  const uint32_t a_narr = smem_u32(&narr[0][0]);

  const int eb = tid & 1, erow = tid >> 1;             // epilogue mapping (tid<128)
  const int dest = tid >> 5, chunk = tid & 31;         // push mapping (256 threads)
  const int pb = chunk >> 4, pq = chunk & 15;
  const uint32_t e_off = (uint32_t)(pb*HID + xpos(rank*16 + pq)*4)*4u;
  const int hk   = rank*64 + erow;
  const int hidx = eb*HID + xpos(hk>>2)*4 + (hk&3);

  float xsv=1.f, be0v=0.f, be1v=0.f;
  if (tid<128){
    int bb = b0+eb;
    xsv  = __ldg(&g_xs1[bb*TT]);
    be0v = __ldg(&g_be0[(bb*TT)*HID + rank*64 + erow]);
  }

  for (int t=0;t<TT;t++){
    const int par = t&1;

    {
      float acc[8];
      dot_bf16(wsmC, (const uint8_t*)&hbufP[0][0], rg, kq, acc);
      #pragma unroll
      for (int off=8; off; off>>=1)
        #pragma unroll
        for (int j=0;j<8;j++) acc[j] += __shfl_down_sync(0xffffffffu, acc[j], off);
      if (kq==0){
        #pragma unroll
        for (int j=0;j<4;j++) pout2[rg*4+j] = make_float2(acc[j*2], acc[j*2+1]);
      }
    }
    __syncthreads();
    if (tid<128){
      float pv = eb ? pout2[erow].y : pout2[erow].x;
      float p = tanhf(pv) * xsv;
      float e = be0v - p;
      estageP[eb][erow] = e;
      float q = e*e;
      #pragma unroll
      for (int off=16; off>=2; off>>=1) q += __shfl_xor_sync(0xffffffffu,q,off);
      if ((tid&31)<2) atomicAdd(&normloc[par][tid&1], q);
    }
    __syncthreads();
    {
      float4 v = ((const float4*)estageP)[chunk];
      dsmem_st4(a_ebuf + e_off, (uint32_t)dest, v);
      if (tid<16)
        dsmem_st1(a_narr + (uint32_t)(((tid&1)*CLN + rank)*4), (uint32_t)(tid>>1),
                  normloc[par][tid&1]);
    }
    CLUSTER_ARRIVE();
    if (tid<128)
      be1v = __ldg(&g_be1[((b0+eb)*TT+t)*HID + rank*64 + erow]);
    CLUSTER_WAIT();

    {
      float acc[8];
      dot_bf16(wsmW, (const uint8_t*)&ebufP[0][0], rg, kq, acc);
      #pragma unroll
      for (int off=8; off; off>>=1)
        #pragma unroll
        for (int j=0;j<8;j++) acc[j] += __shfl_down_sync(0xffffffffu, acc[j], off);
      if (kq==0){
        #pragma unroll
        for (int j=0;j<4;j++) pout2[rg*4+j] = make_float2(acc[j*2], acc[j*2+1]);
      }
    }
    __syncthreads();
    if (tid<128){
      float n2 = (narr[eb][0]+narr[eb][1])+(narr[eb][2]+narr[eb][3])
               + (narr[eb][4]+narr[eb][5])+(narr[eb][6]+narr[eb][7]);
      float rel = fminf(sqrtf(n2)/xsv, 4.0f);
      float s = sigm((rel - tauv)/gamv);
      float hold = (&hbufP[0][0])[hidx];
      float eev = eb ? pout2[erow].y : pout2[erow].x;
      float ih = 0.2f*hold + 0.6f*be1v + 0.2f*s*eev;
      float g = s*sa[erow];
      float hn = hold*(1.f-g) + tanhf(ih)*g;
      hstageP[eb][erow] = hn;
      g_h1[((b0+eb)*TT+t)*HID + rank*64 + erow] = hn;
      if (tid<2) normloc[par^1][tid] = 0.f;
    }
    __syncthreads();
    {
      float4 v = ((const float4*)hstageP)[chunk];
      dsmem_st4(a_hbuf + e_off, (uint32_t)dest, v);
    }
    CLUSTER_ARRIVE();
    if (tid<128 && t+1<TT){
      int bb = b0+eb;
      xsv  = __ldg(&g_xs1[bb*TT+t+1]);
      be0v = __ldg(&g_be0[(bb*TT+t+1)*HID + rank*64 + erow]);
    }
    CLUSTER_WAIT();
  }
}

// ---------------- head: 16 rows/block (2 CTA/SM), f32x2 -------------------------
__global__ __launch_bounds__(256) void k_head(const float* __restrict__ hw,
                                              const float* __restrict__ hb,
                                              float* __restrict__ out){
  extern __shared__ __align__(16) float sh[];        // [HROWS][1024]
  __shared__ float sred[4][HROWS][64];
  int tid=threadIdx.x;
  int row0=blockIdx.x*HROWS;
  for (int i=tid;i<HROWS*256;i+=256){                // float4 granularity
    int r=i>>8, j4=i&255;
    float4 v;
    if (j4<128) v = *(const float4*)&g_h1 [(row0+r)*HID + j4*4];
    else        v = *(const float4*)&g_be1[(row0+r)*HID + (j4-128)*4];
    ((float4*)sh)[i] = v;
  }
  __syncthreads();
  int c=tid&63, q=tid>>6;
  unsigned long long acc[HROWS];
  #pragma unroll
  for (int r=0;r<HROWS;r++) acc[r]=0ull;
  const float* wrow = &hw[c*1024 + q*256];
  for (int k4=0;k4<64;k4++){
    ulonglong2 wp = *(const ulonglong2*)(wrow + k4*4);
    #pragma unroll
    for (int r=0;r<HROWS;r++){
      ulonglong2 xp = *(const ulonglong2*)&sh[r*1024 + q*256 + k4*4];
      ffma2(acc[r], wp.x, xp.x); ffma2(acc[r], wp.y, xp.y);
    }
  }
  #pragma unroll
  for (int r=0;r<HROWS;r++) sred[q][r][c]=hsum2(acc[r]);
  __syncthreads();
  for (int i=tid;i<HROWS*64;i+=256){
    int r=i>>6, cc=i&63;
    out[(row0+r)*NCLS+cc] = sred[0][r][cc]+sred[1][r][cc]
                          + sred[2][r][cc]+sred[3][r][cc] + __ldg(&hb[cc]);
  }
}

// ---------------- launch ----------------
extern "C" void kernel_launch(void* const* d_in, const int* in_sizes, int n_in,
                              void* d_out, int out_size){
  const float* feats=(const float*)d_in[0];
  const float* B0  =(const float*)d_in[2];
  const float* C1  =(const float*)d_in[7];
  const float* B1  =(const float*)d_in[8];
  const float* W1  =(const float*)d_in[9];
  const float* a1  =(const float*)d_in[10];
  const float* tau1=(const float*)d_in[11];
  const float* gam1=(const float*)d_in[12];
  const float* hw  =(const float*)d_in[13];
  const float* hb  =(const float*)d_in[14];
  float* out=(float*)d_out;

  static int smem_set = 0;
  if (!smem_set){
    cudaFuncSetAttribute(k_serial, cudaFuncAttributeMaxDynamicSharedMemorySize, DYNSM);
    cudaFuncSetAttribute(k_head,   cudaFuncAttributeMaxDynamicSharedMemorySize, HEAD_DYN);
    smem_set = 1;
  }

  k_front <<<NROW/16,256>>>(feats,B0,B1);
  k_serial<<<NCTA,256,DYNSM>>>(C1,W1,a1,tau1,gam1);
  k_head  <<<NROW/HROWS,256,HEAD_DYN>>>(hw,hb,out);
}